// round 6
// baseline (speedup 1.0000x reference)
#include <cuda_runtime.h>
#include <cstdint>

// TVConv: per-pixel spatially-varying 3x3 depthwise conv, zero padding.
// x:           (B=8, C=96, H=128, W=128) fp32
// weight_maps: (1,   C=96, 3, 3, H, W)   fp32  (batch-invariant)
// out:         (B, C, H, W) fp32
//
// R4->R5: the 9 float4 weight taps move from registers (36 regs -> occ
// capped at 42.6%) into THREAD-PRIVATE shared memory (each thread writes
// and re-reads only its own 16B lane slice: no syncs, conflict-free
// LDS.128). Freed registers fund an explicit next-batch prefetch (b+1's
// three x-rows in flight while b computes) -> per-warp MLP ~6.
// __launch_bounds__(128,10): <=51 regs, 18.4KB smem => 1280 thr/SM (62.5%).

namespace {
constexpr int B = 8;
constexpr int C = 96;
constexpr int H = 128;
constexpr int W = 128;
constexpr int HW = H * W;
constexpr int WARPS = 4;
constexpr int THREADS = WARPS * 32;
constexpr int NBLOCKS = C * H / WARPS;   // 3072
}

__device__ __forceinline__ float4 ldg4(const float* p) {
    return *reinterpret_cast<const float4*>(p);
}

// One input row's contribution. Weights come from thread-private smem:
// swrow points at tap (i*3+0) for this thread's 4 pixels; taps j=0,1,2
// are +0, +128, +256 floats apart.
__device__ __forceinline__ void accum_row(
    float4 r, const float* swrow,
    float& a0, float& a1, float& a2, float& a3, int lane)
{
    float left  = __shfl_up_sync(0xffffffffu,  r.w, 1);
    float right = __shfl_down_sync(0xffffffffu, r.x, 1);
    if (lane == 0)  left  = 0.f;   // w = -1  -> zero pad
    if (lane == 31) right = 0.f;   // w = 128 -> zero pad
    float4 k0 = *reinterpret_cast<const float4*>(swrow);
    float4 k1 = *reinterpret_cast<const float4*>(swrow + 128);
    float4 k2 = *reinterpret_cast<const float4*>(swrow + 256);
    a0 = fmaf(k0.x, left, fmaf(k1.x, r.x, fmaf(k2.x, r.y, a0)));
    a1 = fmaf(k0.y, r.x,  fmaf(k1.y, r.y, fmaf(k2.y, r.z, a1)));
    a2 = fmaf(k0.z, r.y,  fmaf(k1.z, r.z, fmaf(k2.z, r.w, a2)));
    a3 = fmaf(k0.w, r.z,  fmaf(k1.w, r.w, fmaf(k2.w, right, a3)));
}

__global__ __launch_bounds__(THREADS, 10) void tvconv_kernel(
    const float* __restrict__ x,
    const float* __restrict__ wm,
    float* __restrict__ out)
{
    __shared__ float sw[WARPS][9][W];   // 18432 B

    int lane = threadIdx.x & 31;
    int wid  = threadIdx.x >> 5;
    int t    = blockIdx.x * WARPS + wid;   // (c,h) row index
    int h    = t % H;
    int c    = t / H;
    int w0   = lane * 4;

    // ---- stage this thread's 9 weight taps into its private smem slice ----
    const float* wbase = wm + (size_t)c * 9 * HW + (size_t)h * W + w0;
    float* swp = &sw[wid][0][w0];
#pragma unroll
    for (int k = 0; k < 9; k++) {
        float4 wv = ldg4(wbase + (size_t)k * HW);
        *reinterpret_cast<float4*>(swp + k * W) = wv;
    }
    // thread-private region: no __syncthreads needed.

    const size_t chw = (size_t)c * HW + (size_t)h * W + w0;
    const bool has_up = (h > 0), has_dn = (h < H - 1);
    const float4 z4 = make_float4(0.f, 0.f, 0.f, 0.f);

    // prime b = 0
    const float* xp = x + chw;
    float4 c1 = ldg4(xp);
    float4 c0 = has_up ? ldg4(xp - W) : z4;
    float4 c2 = has_dn ? ldg4(xp + W) : z4;

#pragma unroll
    for (int b = 0; b < B; b++) {
        float4 n0 = z4, n1 = z4, n2 = z4;
        if (b + 1 < B) {               // prefetch next batch's rows
            const float* xn = x + (size_t)(b + 1) * C * HW + chw;
            n1 = ldg4(xn);
            n0 = has_up ? ldg4(xn - W) : z4;
            n2 = has_dn ? ldg4(xn + W) : z4;
        }

        float a0 = 0.f, a1 = 0.f, a2 = 0.f, a3 = 0.f;
        accum_row(c0, swp + 0 * W, a0, a1, a2, a3, lane);
        accum_row(c1, swp + 3 * W, a0, a1, a2, a3, lane);
        accum_row(c2, swp + 6 * W, a0, a1, a2, a3, lane);

        *reinterpret_cast<float4*>(out + (size_t)b * C * HW + chw) =
            make_float4(a0, a1, a2, a3);

        c0 = n0; c1 = n1; c2 = n2;
    }
}

extern "C" void kernel_launch(void* const* d_in, const int* in_sizes, int n_in,
                              void* d_out, int out_size)
{
    const float* x  = (const float*)d_in[0];
    const float* wm = (const float*)d_in[1];
    float* out      = (float*)d_out;

    tvconv_kernel<<<NBLOCKS, THREADS>>>(x, wm, out);
}

// round 7
// speedup vs baseline: 1.0169x; 1.0169x over previous
#include <cuda_runtime.h>
#include <cstdint>

// TVConv: per-pixel spatially-varying 3x3 depthwise conv, zero padding.
// x:           (B=8, C=96, H=128, W=128) fp32
// weight_maps: (1,   C=96, 3, 3, H, W)   fp32  (batch-invariant)
// out:         (B, C, H, W) fp32
//
// R5 lesson: weights must stay REGISTER-resident (smem re-reads killed it).
// R6: 2 px/thread -> 9 float2 weight taps = 18 regs (vs 36), total ~45 regs
// -> 1280 thr/SM (62.5% occ) with launch_bounds(256,5). A warp covers 64 px
// (half a row): interior halo via 2 shfls/row, the half-row seam lanes
// (0 and 31) fetch one scalar halo each from gmem (L1/L2-hot line).

namespace {
constexpr int B = 8;
constexpr int C = 96;
constexpr int H = 128;
constexpr int W = 128;
constexpr int HW = H * W;
constexpr int THREADS = 256;
constexpr int NTHREADS_TOTAL = C * H * (W / 2);   // 786432
constexpr int NBLOCKS = NTHREADS_TOTAL / THREADS; // 3072
}

// Load one input row's float2 + resolve left/right halo scalars.
// Must be called by all 32 lanes (uses full-mask shfl); h is warp-uniform.
__device__ __forceinline__ void load_row(
    const float* __restrict__ xrow, int w0, int lane,
    float2& r, float& lf, float& rt)
{
    r  = *reinterpret_cast<const float2*>(xrow + w0);
    lf = __shfl_up_sync(0xffffffffu,  r.y, 1);
    rt = __shfl_down_sync(0xffffffffu, r.x, 1);
    if (lane == 0)  lf = (w0 == 0)     ? 0.f : __ldg(xrow + w0 - 1);
    if (lane == 31) rt = (w0 + 2 >= W) ? 0.f : __ldg(xrow + w0 + 2);
}

__global__ __launch_bounds__(THREADS, 5) void tvconv_kernel(
    const float* __restrict__ x,
    const float* __restrict__ wm,
    float* __restrict__ out)
{
    int idx  = blockIdx.x * THREADS + threadIdx.x;
    int lane = threadIdx.x & 31;
    int wg   = idx & 63;          // 2-px group within row
    int w0   = wg * 2;
    int row  = idx >> 6;          // (c,h)
    int h    = row % H;
    int c    = row / H;

    // ---- 9 weight taps for these 2 pixels, register-resident,
    //      amortized over all 8 batches ----
    const float* wbase = wm + (size_t)c * 9 * HW + (size_t)h * W + w0;
    float2 wt[9];
#pragma unroll
    for (int k = 0; k < 9; k++)
        wt[k] = *reinterpret_cast<const float2*>(wbase + (size_t)k * HW);

    const size_t chw = (size_t)c * HW + (size_t)h * W;   // row base
    const bool has_up = (h > 0), has_dn = (h < H - 1);

#pragma unroll 2
    for (int b = 0; b < B; b++) {
        const float* xrow = x + (size_t)b * C * HW + chw;

        float2 r0, r1, r2;
        float l0 = 0.f, l1, l2 = 0.f, t0 = 0.f, t1, t2 = 0.f;
        r0 = make_float2(0.f, 0.f);
        r2 = make_float2(0.f, 0.f);

        load_row(xrow, w0, lane, r1, l1, t1);
        if (has_up) load_row(xrow - W, w0, lane, r0, l0, t0);
        if (has_dn) load_row(xrow + W, w0, lane, r2, l2, t2);

        float a0 = 0.f, a1 = 0.f;
        a0 = fmaf(wt[0].x, l0,   fmaf(wt[1].x, r0.x, fmaf(wt[2].x, r0.y, a0)));
        a1 = fmaf(wt[0].y, r0.x, fmaf(wt[1].y, r0.y, fmaf(wt[2].y, t0,   a1)));
        a0 = fmaf(wt[3].x, l1,   fmaf(wt[4].x, r1.x, fmaf(wt[5].x, r1.y, a0)));
        a1 = fmaf(wt[3].y, r1.x, fmaf(wt[4].y, r1.y, fmaf(wt[5].y, t1,   a1)));
        a0 = fmaf(wt[6].x, l2,   fmaf(wt[7].x, r2.x, fmaf(wt[8].x, r2.y, a0)));
        a1 = fmaf(wt[6].y, r2.x, fmaf(wt[7].y, r2.y, fmaf(wt[8].y, t2,   a1)));

        *reinterpret_cast<float2*>(out + (size_t)b * C * HW + chw + w0) =
            make_float2(a0, a1);
    }
}

extern "C" void kernel_launch(void* const* d_in, const int* in_sizes, int n_in,
                              void* d_out, int out_size)
{
    const float* x  = (const float*)d_in[0];
    const float* wm = (const float*)d_in[1];
    float* out      = (float*)d_out;

    tvconv_kernel<<<NBLOCKS, THREADS>>>(x, wm, out);
}

// round 8
// speedup vs baseline: 3.2656x; 3.2114x over previous
#include <cuda_runtime.h>
#include <cstdint>

// TVConv: per-pixel spatially-varying 3x3 depthwise conv, zero padding.
// x:           (B=8, C=96, H=128, W=128) fp32
// weight_maps: (1,   C=96, 3, 3, H, W)   fp32  (batch-invariant)
// out:         (B, C, H, W) fp32
//
// R5/R6 lessons: weights must stay register-resident AND px/thread must
// stay at 4 (fewer threads => less per-byte instruction overhead).
// R7 = R4 + (a) explicit next-batch prefetch with launch_bounds(256,3)
// so ptxas has register headroom (R4 was pinned at 63 and couldn't batch
// loads across b) -> 6 outstanding loads/thread instead of 3;
// (b) __ldcs on weights (read exactly once, keep them out of L2) and
// __stcs on out (write-only) so L2 capacity serves x's 3x h-reuse.

namespace {
constexpr int B = 8;
constexpr int C = 96;
constexpr int H = 128;
constexpr int W = 128;
constexpr int HW = H * W;
constexpr int THREADS = 256;
constexpr int NTHREADS_TOTAL = C * H * (W / 4);   // 393216
constexpr int NBLOCKS = NTHREADS_TOTAL / THREADS; // 1536
}

__device__ __forceinline__ float4 ldg4(const float* p) {
    return *reinterpret_cast<const float4*>(p);
}

__device__ __forceinline__ void accum_row(
    float4 r, float4 k0, float4 k1, float4 k2,
    float& a0, float& a1, float& a2, float& a3, int lane)
{
    float left  = __shfl_up_sync(0xffffffffu,  r.w, 1);
    float right = __shfl_down_sync(0xffffffffu, r.x, 1);
    if (lane == 0)  left  = 0.f;   // w = -1  -> zero pad
    if (lane == 31) right = 0.f;   // w = 128 -> zero pad
    a0 = fmaf(k0.x, left, fmaf(k1.x, r.x, fmaf(k2.x, r.y, a0)));
    a1 = fmaf(k0.y, r.x,  fmaf(k1.y, r.y, fmaf(k2.y, r.z, a1)));
    a2 = fmaf(k0.z, r.y,  fmaf(k1.z, r.z, fmaf(k2.z, r.w, a2)));
    a3 = fmaf(k0.w, r.z,  fmaf(k1.w, r.w, fmaf(k2.w, right, a3)));
}

__global__ __launch_bounds__(THREADS, 3) void tvconv_kernel(
    const float* __restrict__ x,
    const float* __restrict__ wm,
    float* __restrict__ out)
{
    int idx  = blockIdx.x * THREADS + threadIdx.x;
    int lane = threadIdx.x & 31;       // == w4 (W/4 == 32)
    int t    = idx >> 5;
    int h    = t % H;
    int c    = t / H;
    int w0   = lane * 4;

    // ---- 9 weight taps, register-resident, streaming loads (no reuse) ----
    const float* wbase = wm + (size_t)c * 9 * HW + (size_t)h * W + w0;
    float4 wt[9];
#pragma unroll
    for (int k = 0; k < 9; k++)
        wt[k] = __ldcs(reinterpret_cast<const float4*>(wbase + (size_t)k * HW));

    const size_t chw = (size_t)c * HW + (size_t)h * W + w0;
    const bool has_up = (h > 0), has_dn = (h < H - 1);
    const float4 z4 = make_float4(0.f, 0.f, 0.f, 0.f);

    // prime batch 0
    const float* xp = x + chw;
    float4 c1 = ldg4(xp);
    float4 c0 = has_up ? ldg4(xp - W) : z4;
    float4 c2 = has_dn ? ldg4(xp + W) : z4;

#pragma unroll
    for (int b = 0; b < B; b++) {
        float4 n0 = z4, n1 = z4, n2 = z4;
        if (b + 1 < B) {               // prefetch next batch's 3 rows
            const float* xn = x + (size_t)(b + 1) * C * HW + chw;
            n1 = ldg4(xn);
            n0 = has_up ? ldg4(xn - W) : z4;
            n2 = has_dn ? ldg4(xn + W) : z4;
        }

        float a0 = 0.f, a1 = 0.f, a2 = 0.f, a3 = 0.f;
        accum_row(c0, wt[0], wt[1], wt[2], a0, a1, a2, a3, lane);
        accum_row(c1, wt[3], wt[4], wt[5], a0, a1, a2, a3, lane);
        accum_row(c2, wt[6], wt[7], wt[8], a0, a1, a2, a3, lane);

        __stcs(reinterpret_cast<float4*>(out + (size_t)b * C * HW + chw),
               make_float4(a0, a1, a2, a3));

        c0 = n0; c1 = n1; c2 = n2;
    }
}

extern "C" void kernel_launch(void* const* d_in, const int* in_sizes, int n_in,
                              void* d_out, int out_size)
{
    const float* x  = (const float*)d_in[0];
    const float* wm = (const float*)d_in[1];
    float* out      = (float*)d_out;

    tvconv_kernel<<<NBLOCKS, THREADS>>>(x, wm, out);
}